// round 8
// baseline (speedup 1.0000x reference)
#include <cuda_runtime.h>
#include <cuda_bf16.h>
#include <cfloat>
#include <cstdint>

#define NUM_HEADS 4
#define OUT_DIM   256
#define HID       512
#define NQ        256
#define TOPK      16
#define N_MEM_MAX 500000
#define CAND      32
#define CPB       4                       // candidates per (query, half, block)
#define NBLK_MAX  152
#define POOL_MAX  (2 * NBLK_MAX * CPB)    // 1216 per query
#define PMAX_PAD  1280                    // 5 * 256

// ---------------- static scratch ---------------------------------------------
__device__ __align__(16) float          g_qpre[64 * NUM_HEADS * OUT_DIM];
__device__ __align__(16) float          g_q [NQ * OUT_DIM];
__device__ __align__(16) __nv_bfloat16  g_qb[NQ * OUT_DIM];
__device__ float g_cand_val[NQ * POOL_MAX];
__device__ int   g_cand_idx[NQ * POOL_MAX];

// ---------------- helpers ------------------------------------------------------
__device__ __forceinline__ uint32_t smem_u32(const void* p) {
    return (uint32_t)__cvta_generic_to_shared(p);
}
// pack high halves of two fp32 -> bf16x2 (truncation; pure ALU)
__device__ __forceinline__ uint32_t bf16x2_trunc(float lo, float hi) {
    uint32_t r;
    asm("prmt.b32 %0, %1, %2, 0x7632;" : "=r"(r) : "r"(__float_as_uint(lo)), "r"(__float_as_uint(hi)));
    return r;
}
__device__ __forceinline__ void ldsm_x4(uint32_t& r0, uint32_t& r1, uint32_t& r2, uint32_t& r3,
                                        uint32_t addr) {
    asm volatile("ldmatrix.sync.aligned.m8n8.x4.shared.b16 {%0,%1,%2,%3}, [%4];"
                 : "=r"(r0), "=r"(r1), "=r"(r2), "=r"(r3) : "r"(addr));
}
__device__ __forceinline__ void mma_bf16(float* d,
                                         uint32_t a0, uint32_t a1, uint32_t a2, uint32_t a3,
                                         uint32_t b0, uint32_t b1) {
    asm volatile("mma.sync.aligned.m16n8k16.row.col.f32.bf16.bf16.f32 "
                 "{%0,%1,%2,%3}, {%4,%5,%6,%7}, {%8,%9}, {%0,%1,%2,%3};"
                 : "+f"(d[0]), "+f"(d[1]), "+f"(d[2]), "+f"(d[3])
                 : "r"(a0), "r"(a1), "r"(a2), "r"(a3), "r"(b0), "r"(b1));
}
__device__ __forceinline__ unsigned long long sort_key(float v, int idx) {
    uint32_t fb = __float_as_uint(v);
    fb ^= (fb & 0x80000000u) ? 0xFFFFFFFFu : 0x80000000u;
    return ((unsigned long long)fb << 32) | (uint32_t)(~idx);
}

// ---------------- K1a: proj = hidden @ Wp + bp (128 blocks) -------------------
__global__ __launch_bounds__(256) void proj_kernel(const float* __restrict__ hidden,
                                                   const float* __restrict__ Wp,
                                                   const float* __restrict__ bp) {
    const int tid = threadIdx.x;
    const int jb = blockIdx.x & 31, bh = blockIdx.x >> 5;
    const int j  = jb * 32 + (tid & 31);
    const int b0 = bh * 16 + (tid >> 5) * 2;
    float acc0 = 0.f, acc1 = 0.f;
#pragma unroll 4
    for (int k = 0; k < HID; k++) {
        const float wv = __ldg(&Wp[k * (NUM_HEADS * OUT_DIM) + j]);
        acc0 = fmaf(__ldg(&hidden[(b0 + 0) * HID + k]), wv, acc0);
        acc1 = fmaf(__ldg(&hidden[(b0 + 1) * HID + k]), wv, acc1);
    }
    const float bias = __ldg(&bp[j]);
    g_qpre[(b0 + 0) * (NUM_HEADS * OUT_DIM) + j] = acc0 + bias;
    g_qpre[(b0 + 1) * (NUM_HEADS * OUT_DIM) + j] = acc1 + bias;
}

// ---------------- K1b: layernorm ----------------------------------------------
__global__ __launch_bounds__(256) void ln_kernel() {
    __shared__ float red[OUT_DIM];
    const int qidx = blockIdx.x;
    const int h = qidx >> 6, b = qidx & 63, d = threadIdx.x;

    const float x = g_qpre[b * (NUM_HEADS * OUT_DIM) + h * OUT_DIM + d];
    red[d] = x; __syncthreads();
    for (int s = 128; s > 0; s >>= 1) { if (d < s) red[d] += red[d + s]; __syncthreads(); }
    const float mean = red[0] * (1.0f / OUT_DIM);
    __syncthreads();
    const float dx = x - mean;
    red[d] = dx * dx; __syncthreads();
    for (int s = 128; s > 0; s >>= 1) { if (d < s) red[d] += red[d + s]; __syncthreads(); }
    const float var = red[0] * (1.0f / OUT_DIM);

    const float o = dx * rsqrtf(var + 1e-5f);
    g_q [qidx * OUT_DIM + d] = o;
    g_qb[qidx * OUT_DIM + d] = __float2bfloat16(o);
}

// ---------------- K2: bf16 mma, 64-row tiles, 32x32 warp tiles ----------------
#define K2_THREADS 512
#define TROWS 64
#define LDB   264                        // bf16 elems per row (528B), ldsm conflict-free
#define LDBB  (LDB * 2)                  // 528
#define B_BYTES (NQ * LDBB)              // 135168
#define A_BYTES (TROWS * LDBB)           // 33792
#define SBP   260
#define K2_SMEM (B_BYTES + 2 * A_BYTES)  // 202752 (Sb aliases A[cur])

#define INS4(v, r)                                                        \
    do {                                                                  \
        t4v[tminpos] = (v); t4i[tminpos] = (r);                           \
        tmin = t4v[0]; tminpos = 0;                                       \
        _Pragma("unroll")                                                 \
        for (int jj = 1; jj < CPB; jj++)                                  \
            if (t4v[jj] < tmin) { tmin = t4v[jj]; tminpos = jj; }         \
    } while (0)

__global__ __launch_bounds__(K2_THREADS, 1) void score_kernel(const float* __restrict__ mem,
                                                              int n_mem, int ntiles) {
    extern __shared__ char sm[];
    char* Bs = sm;                        // queries bf16 [256][LDB]
    const uint32_t sb = smem_u32(sm);

    const int tid = threadIdx.x, lane = tid & 31, w = tid >> 5;   // 16 warps
    const int rg = w >> 3, qg = w & 7;    // warp tile: rows rg*32..+31, q qg*32..+31

    // B fill: 256 queries x 512B bf16
    {
        const uint2* src = (const uint2*)g_qb;
        for (int p = tid; p < NQ * 64; p += K2_THREADS) {
            const int q = p >> 6, c4 = p & 63;
            *(uint2*)(Bs + q * LDBB + c4 * 8) = src[p];
        }
    }

    // selection state: thread covers query (tid&255), half (tid>>8) -> 32 rows
    const int myq = tid & 255, half = tid >> 8;
    float t4v[CPB]; int t4i[CPB];
#pragma unroll
    for (int j = 0; j < CPB; j++) { t4v[j] = -FLT_MAX; t4i[j] = 0x7FFFFFFF; }
    float tmin = -FLT_MAX; int tminpos = 0;

    // A loader: thread -> row tid>>3 (0..63), float col (tid&7)*32
    const int ar = tid >> 3, ac = (tid & 7) * 32;
    const uint32_t asts0 = sb + B_BYTES + ar * LDBB + ac * 2;

    float4 f[8];
#define LDG_T(tl)                                                                   \
    do {                                                                            \
        const int rg_ = (tl) * TROWS + ar;                                          \
        if (rg_ < n_mem) {                                                          \
            const float4* s = (const float4*)(mem + (size_t)rg_ * OUT_DIM + ac);    \
            f[0] = s[0]; f[1] = s[1]; f[2] = s[2]; f[3] = s[3];                     \
            f[4] = s[4]; f[5] = s[5]; f[6] = s[6]; f[7] = s[7];                     \
        } else {                                                                    \
            _Pragma("unroll")                                                       \
            for (int i_ = 0; i_ < 8; i_++) f[i_] = make_float4(0.f, 0.f, 0.f, 0.f); \
        }                                                                           \
    } while (0)

#define STS_T(bufi)                                                                 \
    do {                                                                            \
        const uint32_t d = asts0 + (bufi) * A_BYTES;                                \
        _Pragma("unroll")                                                           \
        for (int i_ = 0; i_ < 4; i_++) {                                            \
            uint4 o;                                                                \
            o.x = bf16x2_trunc(f[2 * i_].x, f[2 * i_].y);                           \
            o.y = bf16x2_trunc(f[2 * i_].z, f[2 * i_].w);                           \
            o.z = bf16x2_trunc(f[2 * i_ + 1].x, f[2 * i_ + 1].y);                   \
            o.w = bf16x2_trunc(f[2 * i_ + 1].z, f[2 * i_ + 1].w);                   \
            asm volatile("st.shared.v4.b32 [%0], {%1,%2,%3,%4};" ::                 \
                "r"(d + i_ * 16), "r"(o.x), "r"(o.y), "r"(o.z), "r"(o.w)            \
                : "memory");                                                        \
        }                                                                           \
    } while (0)

    // prologue
    LDG_T(blockIdx.x);
    STS_T(0);
    __syncthreads();

    const uint32_t bB = sb + (qg * 32 + (lane & 15)) * LDBB + (lane >> 4) * 16;

    int it = 0;
    for (int t = blockIdx.x; t < ntiles; t += gridDim.x, it++) {
        const int cur = it & 1;
        const int tn = t + gridDim.x;
        if (tn < ntiles) LDG_T(tn);           // hide LDG under mma

        const uint32_t aB = sb + B_BYTES + cur * A_BYTES
                          + (rg * 32 + (lane & 15)) * LDBB + (lane >> 4) * 16;

        float acc[2][4][4];
#pragma unroll
        for (int mt = 0; mt < 2; mt++)
#pragma unroll
            for (int nt = 0; nt < 4; nt++)
#pragma unroll
                for (int c = 0; c < 4; c++) acc[mt][nt][c] = 0.f;

#pragma unroll
        for (int kt = 0; kt < 16; kt++) {
            uint32_t a0, a1, a2, a3, a4, a5, a6, a7;
            ldsm_x4(a0, a1, a2, a3, aB + kt * 32);
            ldsm_x4(a4, a5, a6, a7, aB + 16 * LDBB + kt * 32);
            uint32_t b0, b1, b2, b3, b4, b5, b6, b7;
            ldsm_x4(b0, b1, b2, b3, bB + kt * 32);
            ldsm_x4(b4, b5, b6, b7, bB + 16 * LDBB + kt * 32);
            mma_bf16(acc[0][0], a0, a1, a2, a3, b0, b2);
            mma_bf16(acc[0][1], a0, a1, a2, a3, b1, b3);
            mma_bf16(acc[0][2], a0, a1, a2, a3, b4, b6);
            mma_bf16(acc[0][3], a0, a1, a2, a3, b5, b7);
            mma_bf16(acc[1][0], a4, a5, a6, a7, b0, b2);
            mma_bf16(acc[1][1], a4, a5, a6, a7, b1, b3);
            mma_bf16(acc[1][2], a4, a5, a6, a7, b4, b6);
            mma_bf16(acc[1][3], a4, a5, a6, a7, b5, b7);
        }
        __syncthreads();                      // (1) all warps done reading A[cur]

        // scores -> Sb (aliased into A[cur]) [64 r][256 q] bf16
        __nv_bfloat16* Sb = (__nv_bfloat16*)(sm + B_BYTES + cur * A_BYTES);
#pragma unroll
        for (int mt = 0; mt < 2; mt++) {
            const int rl = rg * 32 + mt * 16 + (lane >> 2);
#pragma unroll
            for (int nt = 0; nt < 4; nt++) {
                const int q = qg * 32 + nt * 8 + (lane & 3) * 2;
                *(__nv_bfloat162*)(Sb + rl * SBP + q) =
                    __float22bfloat162_rn(make_float2(acc[mt][nt][0], acc[mt][nt][1]));
                *(__nv_bfloat162*)(Sb + (rl + 8) * SBP + q) =
                    __float22bfloat162_rn(make_float2(acc[mt][nt][2], acc[mt][nt][3]));
            }
        }
        if (tn < ntiles) STS_T(cur ^ 1);      // stage next tile into other buffer
        __syncthreads();                      // (2) Sb + A[cur^1] visible

        // fused selection: 2 threads per query, 32 rows each
        {
            const int rb = t * TROWS + half * 32;
            const int rcap = n_mem - rb;
#pragma unroll 4
            for (int r = 0; r < 32; r++) {
                const float v = __bfloat162float(Sb[(half * 32 + r) * SBP + myq]);
                if (v > tmin && r < rcap) INS4(v, rb + r);
            }
        }
        // no trailing barrier: next iteration's barrier (1) orders Sb reuse
    }

    const int ob = ((myq * 2 + half) * gridDim.x + blockIdx.x) * CPB;
#pragma unroll
    for (int j = 0; j < CPB; j++) { g_cand_val[ob + j] = t4v[j]; g_cand_idx[ob + j] = t4i[j]; }
#undef LDG_T
#undef STS_T
}

// ---------------- K3: rank-select top-32 -> exact rescore -> top-16 ------------
__global__ __launch_bounds__(256) void final_kernel(const float* __restrict__ mem,
                                                    float* __restrict__ out,
                                                    int n_mem, int P) {
    __shared__ unsigned long long keys[PMAX_PAD];
    __shared__ int   si[PMAX_PAD];
    __shared__ int   ci[CAND];
    __shared__ float ev[CAND];
    __shared__ unsigned long long k2[CAND];
    __shared__ float wv[TOPK]; __shared__ int wi[TOPK];

    const int q = blockIdx.x, tid = threadIdx.x, lane = tid & 31, w = tid >> 5;

    for (int j = tid; j < PMAX_PAD; j += 256) {
        if (j < P) {
            const float v = g_cand_val[q * P + j];
            const int  id = g_cand_idx[q * P + j];
            keys[j] = sort_key(v, id);
            si[j] = id;
        } else { keys[j] = 0ull; si[j] = 0x7FFFFFFF; }
    }
    if (tid < CAND) ci[tid] = 0x7FFFFFFF;
    __syncthreads();

    // rank-count: thread owns 5 candidates; scan batched by 8 to hide LDS latency
    unsigned long long mk[5]; int mrank[5];
#pragma unroll
    for (int i = 0; i < 5; i++) { mk[i] = keys[tid + i * 256]; mrank[i] = 0; }
    for (int j = 0; j < PMAX_PAD; j += 8) {
        unsigned long long kk[8];
#pragma unroll
        for (int u = 0; u < 8; u++) kk[u] = keys[j + u];
#pragma unroll
        for (int i = 0; i < 5; i++) {
            int add = 0;
#pragma unroll
            for (int u = 0; u < 8; u++) add += (kk[u] > mk[i]) ? 1 : 0;
            mrank[i] += add;
        }
    }
#pragma unroll
    for (int i = 0; i < 5; i++)
        if (mrank[i] < CAND && mk[i] != 0ull) ci[mrank[i]] = si[tid + i * 256];
    __syncthreads();

    // exact fp32 rescore of 32 candidates
    const float* qv = g_q + q * OUT_DIM;
    for (int c = w; c < CAND; c += 8) {
        const int id = ci[c];
        float sum = 0.f;
        if (id < n_mem) {
            const float* row = mem + (size_t)id * OUT_DIM;
#pragma unroll
            for (int d = lane; d < OUT_DIM; d += 32) sum += row[d] * qv[d];
        }
#pragma unroll
        for (int o = 16; o; o >>= 1) sum += __shfl_xor_sync(0xffffffffu, sum, o);
        if (lane == 0) ev[c] = (id < n_mem) ? sum : -FLT_MAX;
    }
    __syncthreads();

    if (tid < CAND) k2[tid] = sort_key(ev[tid], ci[tid]);
    __syncthreads();
    if (tid < CAND) {
        const unsigned long long mine = k2[tid];
        int r = 0;
#pragma unroll
        for (int j = 0; j < CAND; j++)
            if (k2[j] > mine) r++;
        if (r < TOPK) { wv[r] = ev[tid]; wi[r] = ci[tid]; }
    }
    __syncthreads();

    float* out_scores = out;
    float* out_idx    = out + NQ * TOPK;
    float* out_feats  = out + 2 * NQ * TOPK;

    if (tid < TOPK) {
        out_scores[q * TOPK + tid] = wv[tid];
        out_idx[q * TOPK + tid]    = (float)wi[tid];
    }
#pragma unroll 1
    for (int kk = 0; kk < TOPK; kk++)
        out_feats[(size_t)(q * TOPK + kk) * OUT_DIM + tid] = mem[(size_t)wi[kk] * OUT_DIM + tid];
}

// ---------------- launch ------------------------------------------------------
extern "C" void kernel_launch(void* const* d_in, const int* in_sizes, int n_in,
                              void* d_out, int out_size) {
    const float* hidden = (const float*)d_in[0];
    const float* Wp     = (const float*)d_in[1];
    const float* bp     = (const float*)d_in[2];
    const float* mem    = (const float*)d_in[3];
    int n_mem = in_sizes[3] / OUT_DIM;
    if (n_mem > N_MEM_MAX) n_mem = N_MEM_MAX;
    const int ntiles = (n_mem + TROWS - 1) / TROWS;

    int dev = 0;
    cudaGetDevice(&dev);
    int nsm = 148;
    cudaDeviceGetAttribute(&nsm, cudaDevAttrMultiProcessorCount, dev);
    if (nsm < 1) nsm = 148;
    if (nsm > NBLK_MAX) nsm = NBLK_MAX;
    if (nsm > ntiles) nsm = ntiles;

    cudaFuncSetAttribute(score_kernel, cudaFuncAttributeMaxDynamicSharedMemorySize, K2_SMEM);

    proj_kernel<<<128, 256>>>(hidden, Wp, bp);
    ln_kernel<<<NQ, 256>>>();
    score_kernel<<<nsm, K2_THREADS, K2_SMEM>>>(mem, n_mem, ntiles);
    final_kernel<<<NQ, 256>>>(mem, (float*)d_out, n_mem, 2 * nsm * CPB);
}